// round 13
// baseline (speedup 1.0000x reference)
#include <cuda_runtime.h>
#include <math.h>

// Problem dims
#define T_STEPS 8
#define N_PED   2048
#define H_DIM   128
#define D_IN    64
#define G4H     512   // 4*H
#define N_GRP   64
#define GRP_N   32
#define DD_DIM  64
#define NH      4

typedef unsigned long long ull;

// packed f32x2 helpers (sm_100+)
#define FMA2(d, a, b, c) asm("fma.rn.f32x2 %0, %1, %2, %3;" : "=l"(d) : "l"(a), "l"(b), "l"(c))
#define ADD2(d, a, b) asm("add.rn.f32x2 %0, %1, %2;" : "=l"(d) : "l"(a), "l"(b))
#define PK2(dst, s) do { unsigned _u = __float_as_uint(s); \
    asm("mov.b64 %0, {%1, %1};" : "=l"(dst) : "r"(_u)); } while (0)
#define PKAB(dst, a, b) do { unsigned _ua = __float_as_uint(a), _ub = __float_as_uint(b); \
    asm("mov.b64 %0, {%1, %2};" : "=l"(dst) : "r"(_ua), "r"(_ub)); } while (0)
#define UNPK2(lo, hi, v) do { unsigned _a, _b; \
    asm("mov.b64 {%0, %1}, %2;" : "=r"(_a), "=r"(_b) : "l"(v)); \
    lo = __uint_as_float(_a); hi = __uint_as_float(_b); } while (0)

// ---------------- scratch (device globals; no allocation) ----------------
__device__ __align__(16) float d_wt2 [H_DIM * G4H];   // [k][ch][u]
__device__ __align__(16) float d_wit2[D_IN * G4H];
__device__ __align__(16) float d_bsum2[G4H];          // [ch][u]
__device__ __align__(16) float d_xw [T_STEPS * N_PED * G4H];  // bias + x@W_ih^T, permuted
__device__ __align__(16) float d_h [N_PED * H_DIM];
__device__ __align__(16) float d_th[N_PED * H_DIM];   // tanh(h)
__device__ __align__(16) float d_uv[2 * NH * H_DIM];  // u then v
__device__ __align__(16) float d_gate[N_PED * GRP_N * H_DIM];  // gate[p][j][c]
__device__ __align__(16) float d_m [N_PED * G4H];     // m_cat[p][h*128+f]

// ---------------- fast activations ----------------
__device__ __forceinline__ float sigf(float x) {
    return __fdividef(1.f, 1.f + __expf(-x));
}
__device__ __forceinline__ float tanh_f(float x) {
    return 1.f - __fdividef(2.f, __expf(2.f * x) + 1.f);
}

// ---------------- prep: weight permute (coalesced reads) + bias sum + uv fold ----------------
#define PREP_BLKS 386
__global__ void prep_kernel(const float* __restrict__ W_hh, const float* __restrict__ W_ih,
                            const float* __restrict__ b_ih, const float* __restrict__ b_hh,
                            const float* __restrict__ gat_w, const float* __restrict__ gat_a)
{
    int b = blockIdx.x;
    int tid = threadIdx.x;
    if (b < PREP_BLKS) {
        int i = b * 256 + tid;
        if (i < H_DIM * G4H) {
            int n = i >> 7, k = i & 127;          // coalesced read of W_hh[n][k]
            int ch = n & 127, u = n >> 7;
            d_wt2[k * G4H + ch * 4 + u] = W_hh[n * H_DIM + k];
            return;
        }
        int j = i - H_DIM * G4H;
        if (j < D_IN * G4H) {
            int n = j >> 6, k = j & 63;           // coalesced read of W_ih[n][k]
            int ch = n & 127, u = n >> 7;
            d_wit2[k * G4H + ch * 4 + u] = W_ih[n * D_IN + k];
            return;
        }
        int bb = j - D_IN * G4H;
        if (bb < G4H) {
            int ch = bb >> 2, u = bb & 3;
            int n = u * 128 + ch;
            d_bsum2[bb] = b_ih[n] + b_hh[n];
        }
        return;
    }
    // uv: u_h = w_h @ a1, v_h = w_h @ a2 — 1 warp per dot
    int w = (b - PREP_BLKS) * 8 + (tid >> 5);   // 0..1023
    int lane = tid & 31;
    int sel = w >> 9;
    int h   = (w >> 7) & 3;
    int c   = w & 127;
    const float* a  = gat_a + sel * H_DIM;
    const float* wp = gat_w + ((size_t)h * H_DIM + c) * H_DIM;
    float s = 0.f;
#pragma unroll
    for (int o = lane; o < H_DIM; o += 32) s = fmaf(wp[o], a[o], s);
#pragma unroll
    for (int o = 16; o; o >>= 1) s += __shfl_xor_sync(0xffffffffu, s, o);
    if (lane == 0) d_uv[sel * (NH * H_DIM) + h * H_DIM + c] = s;
}

// ---------------- xw: d_xw[t][p] = bias + embed(obs) @ W_ih^T (permuted layout) ----------------
// grid 512: b -> t = b>>6, rows p0 = (b&63)*32. 512 threads: ch(128) x ty(4 octets of 8 rows).
__global__ __launch_bounds__(512) void xw_kernel(
    const float* __restrict__ obs,
    const float* __restrict__ W_emb, const float* __restrict__ b_emb)
{
    __shared__ __align__(16) ull x_dup[D_IN][32];   // 16 KB, value-duplicated f32x2
    int tid = threadIdx.x;
    int ch = tid & 127, ty = tid >> 7;
    int t  = blockIdx.x >> 6;
    int p0 = (blockIdx.x & 63) * 32;

    for (int i = tid; i < 32 * D_IN; i += 512) {
        int r = i & 31, c = i >> 5;
        const float* op = obs + ((size_t)t * N_PED + p0 + r) * 2;
        float v = fmaxf(fmaf(op[0], W_emb[c], fmaf(op[1], W_emb[64 + c], b_emb[c])), 0.f);
        ull dv; PKAB(dv, v, v);
        x_dup[c][r] = dv;
    }
    ulonglong2 bi = *(const ulonglong2*)&d_bsum2[ch * 4];
    __syncthreads();

    const ulonglong2* wi2 = (const ulonglong2*)d_wit2;
    ull acc[8][2];
#pragma unroll
    for (int p = 0; p < 8; p++) { acc[p][0] = bi.x; acc[p][1] = bi.y; }
#pragma unroll 8
    for (int k = 0; k < D_IN; k++) {
        ulonglong2 wv = wi2[k * 128 + ch];
        const ull* xrow = &x_dup[k][8 * ty];
        ulonglong2 xA = *(const ulonglong2*)&xrow[0];
        ulonglong2 xB = *(const ulonglong2*)&xrow[2];
        ulonglong2 xC = *(const ulonglong2*)&xrow[4];
        ulonglong2 xD = *(const ulonglong2*)&xrow[6];
        FMA2(acc[0][0], xA.x, wv.x, acc[0][0]); FMA2(acc[0][1], xA.x, wv.y, acc[0][1]);
        FMA2(acc[1][0], xA.y, wv.x, acc[1][0]); FMA2(acc[1][1], xA.y, wv.y, acc[1][1]);
        FMA2(acc[2][0], xB.x, wv.x, acc[2][0]); FMA2(acc[2][1], xB.x, wv.y, acc[2][1]);
        FMA2(acc[3][0], xB.y, wv.x, acc[3][0]); FMA2(acc[3][1], xB.y, wv.y, acc[3][1]);
        FMA2(acc[4][0], xC.x, wv.x, acc[4][0]); FMA2(acc[4][1], xC.x, wv.y, acc[4][1]);
        FMA2(acc[5][0], xC.y, wv.x, acc[5][0]); FMA2(acc[5][1], xC.y, wv.y, acc[5][1]);
        FMA2(acc[6][0], xD.x, wv.x, acc[6][0]); FMA2(acc[6][1], xD.x, wv.y, acc[6][1]);
        FMA2(acc[7][0], xD.y, wv.x, acc[7][0]); FMA2(acc[7][1], xD.y, wv.y, acc[7][1]);
    }
#pragma unroll
    for (int p = 0; p < 8; p++) {
        ulonglong2 o2; o2.x = acc[p][0]; o2.y = acc[p][1];
        *(ulonglong2*)&d_xw[((size_t)t * N_PED + p0 + 8 * ty + p) * G4H + ch * 4] = o2;
    }
}

// ---------------- 8-step LSTM, recurrent-only: 512 threads, 8 peds/thread, split-K ----------------
// ch = tid&127, ty = (tid>>7)&1 (ped octet), kh = tid>>8 (K half of 128).
// xw (bias + input GEMM) preloaded per step into regs, folded at finalize.
#define HP 18   // h row pitch in ull
__global__ __launch_bounds__(512) void lstm512x8(
    const float* __restrict__ h0, const float* __restrict__ c0)
{
    extern __shared__ __align__(16) char sraw[];
    ull (*h_dup)[H_DIM][HP] = (ull (*)[H_DIM][HP])sraw;                // 36 KB
    ull (*red)[8][256]      = (ull (*)[8][256])(sraw + 36864);         // 32 KB

    int tid = threadIdx.x;
    int ch = tid & 127;
    int ty = (tid >> 7) & 1;
    int kh = tid >> 8;
    int p0 = blockIdx.x * 16;

    // stage h0 (duplicated)
    for (int i = tid; i < 16 * H_DIM; i += 512) {
        int r = i & 15;
        int k = i >> 4;
        float v = h0[(size_t)(p0 + r) * H_DIM + k];
        ull dv; PKAB(dv, v, v);
        h_dup[0][k][r] = dv;
    }
    // c for the 4 peds this thread finalizes: local q = kh*4 + q'
    float c_reg[4];
#pragma unroll
    for (int q = 0; q < 4; q++)
        c_reg[q] = c0[(size_t)(p0 + 8 * ty + kh * 4 + q) * H_DIM + ch];
    __syncthreads();

    const ulonglong2* wt2 = (const ulonglong2*)d_wt2;   // idx k*128 + ch
    int idx = ty * 128 + ch;
    int kbR = kh * 64;

    for (int t = 0; t < T_STEPS; t++) {
        int cur = t & 1, nxt = cur ^ 1;
        // preload xw for own 4 peds (consumed only at finalize -> latency hidden)
        ulonglong2 xwv[4];
#pragma unroll
        for (int q = 0; q < 4; q++) {
            int pq = kh * 4 + q;
            xwv[q] = *(const ulonglong2*)&d_xw[((size_t)t * N_PED + p0 + 8 * ty + pq) * G4H + ch * 4];
        }
        ull acc[8][2];
#pragma unroll
        for (int p = 0; p < 8; p++) { acc[p][0] = 0ull; acc[p][1] = 0ull; }
        // recurrent: 64 of K=128
#pragma unroll 8
        for (int k = 0; k < 64; k++) {
            int kk = kbR + k;
            ulonglong2 wv = wt2[kk * 128 + ch];
            const ull* hrow = &h_dup[cur][kk][8 * ty];
            ulonglong2 hA = *(const ulonglong2*)&hrow[0];
            ulonglong2 hB = *(const ulonglong2*)&hrow[2];
            ulonglong2 hC = *(const ulonglong2*)&hrow[4];
            ulonglong2 hD = *(const ulonglong2*)&hrow[6];
            FMA2(acc[0][0], hA.x, wv.x, acc[0][0]); FMA2(acc[0][1], hA.x, wv.y, acc[0][1]);
            FMA2(acc[1][0], hA.y, wv.x, acc[1][0]); FMA2(acc[1][1], hA.y, wv.y, acc[1][1]);
            FMA2(acc[2][0], hB.x, wv.x, acc[2][0]); FMA2(acc[2][1], hB.x, wv.y, acc[2][1]);
            FMA2(acc[3][0], hB.y, wv.x, acc[3][0]); FMA2(acc[3][1], hB.y, wv.y, acc[3][1]);
            FMA2(acc[4][0], hC.x, wv.x, acc[4][0]); FMA2(acc[4][1], hC.x, wv.y, acc[4][1]);
            FMA2(acc[5][0], hC.y, wv.x, acc[5][0]); FMA2(acc[5][1], hC.y, wv.y, acc[5][1]);
            FMA2(acc[6][0], hD.x, wv.x, acc[6][0]); FMA2(acc[6][1], hD.x, wv.y, acc[6][1]);
            FMA2(acc[7][0], hD.y, wv.x, acc[7][0]); FMA2(acc[7][1], hD.y, wv.y, acc[7][1]);
        }
        // ship the 4 peds the partner K-half finalizes
        if (kh == 0) {
#pragma unroll
            for (int q = 0; q < 4; q++) {
                red[0][q * 2 + 0][idx] = acc[4 + q][0];
                red[0][q * 2 + 1][idx] = acc[4 + q][1];
            }
        } else {
#pragma unroll
            for (int q = 0; q < 4; q++) {
                red[1][q * 2 + 0][idx] = acc[q][0];
                red[1][q * 2 + 1][idx] = acc[q][1];
            }
        }
        __syncthreads();
        // finalize own 4 peds: recurrent(own half) + recurrent(partner) + xw
#pragma unroll
        for (int q = 0; q < 4; q++) {
            int pq = kh * 4 + q;
            ull a0 = acc[pq][0], a1 = acc[pq][1];
            ADD2(a0, a0, red[1 - kh][q * 2 + 0][idx]);
            ADD2(a1, a1, red[1 - kh][q * 2 + 1][idx]);
            ADD2(a0, a0, xwv[q].x);
            ADD2(a1, a1, xwv[q].y);
            float iv, fv, gv, ov;
            UNPK2(iv, fv, a0);
            UNPK2(gv, ov, a1);
            float cn = sigf(fv) * c_reg[q] + sigf(iv) * tanh_f(gv);
            c_reg[q] = cn;
            float hv = sigf(ov) * tanh_f(cn);
            ull dv; PKAB(dv, hv, hv);
            h_dup[nxt][ch][8 * ty + pq] = dv;
        }
        __syncthreads();
    }
    // final h in buffer 0 (T_STEPS even)
    for (int i = tid; i < 16 * H_DIM; i += 512) {
        int k = i & 127;
        int r = i >> 7;
        float v = __uint_as_float((unsigned)(h_dup[0][k][r] & 0xffffffffull));
        d_h [(size_t)(p0 + r) * H_DIM + k] = v;
        d_th[(size_t)(p0 + r) * H_DIM + k] = tanh_f(v);
    }
}

// ---------------- gate MLP (position-only), standalone ----------------
__global__ __launch_bounds__(256) void gateMLP(
    const float* __restrict__ goal, const float* __restrict__ action,
    const float* __restrict__ W_dist, const float* __restrict__ b_dist,
    const float* __restrict__ W_gate, const float* __restrict__ b_gate)
{
    __shared__ __align__(16) float t_sh[GRP_N * DD_DIM];       // 8KB
    __shared__ __align__(16) float s_sh[2 * DD_DIM];
    __shared__ __align__(16) float r_sh[2 * GRP_N * DD_DIM];   // 16KB
    __shared__ float pax[GRP_N], pay[GRP_N], pgx[GRP_N], pgy[GRP_N];

    int tid = threadIdx.x;
    int b = blockIdx.x;
    int g  = b >> 4;
    int ip = b & 15;
    int half = tid >> 7;
    int c    = tid & 127;
    int i_loc = 2 * ip + half;
    int p = g * GRP_N + i_loc;

    if (tid < GRP_N) {
        int q = g * GRP_N + tid;
        pax[tid] = action[q * 2 + 0]; pay[tid] = action[q * 2 + 1];
        pgx[tid] = goal[q * 2 + 0];   pgy[tid] = goal[q * 2 + 1];
    }
    __syncthreads();
    for (int idx = tid; idx < GRP_N * DD_DIM; idx += 256) {
        int j = idx >> 6, d = idx & 63;
        float t = fmaf(pax[j], W_dist[4 * 64 + d],
                  fmaf(pay[j], W_dist[5 * 64 + d],
                  fmaf(pgx[j], W_dist[6 * 64 + d],
                       pgy[j] * W_dist[7 * 64 + d])));
        t_sh[idx] = t;
    }
    if (tid < 2 * DD_DIM) {
        int hh = tid >> 6, d = tid & 63;
        int il = 2 * ip + hh;
        float s = b_dist[d];
        s = fmaf(pax[il], W_dist[0 * 64 + d], s);
        s = fmaf(pay[il], W_dist[1 * 64 + d], s);
        s = fmaf(pgx[il], W_dist[2 * 64 + d], s);
        s = fmaf(pgy[il], W_dist[3 * 64 + d], s);
        s_sh[tid] = s;
    }
    __syncthreads();
    for (int idx = tid; idx < 2 * GRP_N * DD_DIM; idx += 256) {
        int hh = idx >> 11, jd = idx & 2047;
        r_sh[idx] = fmaxf(s_sh[hh * 64 + (jd & 63)] + t_sh[jd], 0.f);
    }
    __syncthreads();

    float bg = b_gate[c];
    const float* rbase = r_sh + half * GRP_N * DD_DIM;
    float* gout = d_gate + (size_t)p * GRP_N * H_DIM;
#pragma unroll
    for (int jt = 0; jt < 4; jt++) {
        int j0 = jt * 8;
        ull acc2[8];
#pragma unroll
        for (int jj = 0; jj < 8; jj++) acc2[jj] = 0ull;
        for (int d0 = 0; d0 < DD_DIM; d0 += 4) {
            float w0 = W_gate[(d0 + 0) * H_DIM + c];
            float w1 = W_gate[(d0 + 1) * H_DIM + c];
            float w2 = W_gate[(d0 + 2) * H_DIM + c];
            float w3 = W_gate[(d0 + 3) * H_DIM + c];
            ull ww0, ww1;
            PKAB(ww0, w0, w1);
            PKAB(ww1, w2, w3);
#pragma unroll
            for (int jj = 0; jj < 8; jj++) {
                ulonglong2 rv = *(const ulonglong2*)&rbase[(j0 + jj) * DD_DIM + d0];
                FMA2(acc2[jj], rv.x, ww0, acc2[jj]);
                FMA2(acc2[jj], rv.y, ww1, acc2[jj]);
            }
        }
#pragma unroll
        for (int jj = 0; jj < 8; jj++) {
            float lo, hi;
            UNPK2(lo, hi, acc2[jj]);
            gout[(j0 + jj) * H_DIM + c] = sigf(lo + hi + bg);
        }
    }
}

// ---------------- KERNEL B: h-dependent GAT ----------------
__global__ __launch_bounds__(256) void gatB(const float* __restrict__ goal_hidden)
{
    __shared__ __align__(16) float gth[2 * GRP_N * H_DIM];  // 32KB
    __shared__ float ah_sh[2][H_DIM];
    __shared__ float sdot[2][NH][GRP_N];
    __shared__ float alpha[2][NH][GRP_N + 1];
    __shared__ float hsu[2][NH], hsv[2][NH];

    int tid = threadIdx.x;
    int b = blockIdx.x;
    int g  = b >> 4;
    int ip = b & 15;
    int half = tid >> 7;
    int c    = tid & 127;
    int i_loc = 2 * ip + half;
    int p = g * GRP_N + i_loc;

    float ahc = d_h[(size_t)p * H_DIM + c];
    float ghc = goal_hidden[(size_t)p * H_DIM + c];
    ah_sh[half][c] = ahc;

    {
        const float* gp = d_gate + (size_t)p * GRP_N * H_DIM;
        float* dst = gth + half * GRP_N * H_DIM;
#pragma unroll 4
        for (int j = 0; j < GRP_N; j++) {
            float v = gp[j * H_DIM + c] * d_th[(size_t)(g * GRP_N + j) * H_DIM + c];
            dst[j * H_DIM + c] = (j == i_loc) ? ghc : v;
        }
    }
    __syncthreads();

    {
        int t128 = tid & 127, w = t128 >> 5, lane = t128 & 31;
        const float* uh = d_uv + w * H_DIM;
        const float* vh = d_uv + NH * H_DIM + w * H_DIM;
        float u4[4], v4[4], a4[4];
#pragma unroll
        for (int k = 0; k < 4; k++) {
            int cc = lane + 32 * k;
            u4[k] = uh[cc]; v4[k] = vh[cc];
            a4[k] = ah_sh[half][cc];
        }
        float su = 0.f, sv = 0.f;
#pragma unroll
        for (int k = 0; k < 4; k++) { su = fmaf(a4[k], u4[k], su); sv = fmaf(a4[k], v4[k], sv); }
#pragma unroll
        for (int o = 16; o; o >>= 1) {
            su += __shfl_xor_sync(0xffffffffu, su, o);
            sv += __shfl_xor_sync(0xffffffffu, sv, o);
        }
        if (lane == 0) { hsu[half][w] = su; hsv[half][w] = sv; }
        const float* src = gth + half * GRP_N * H_DIM;
        for (int j = 0; j < GRP_N; j++) {
            float s = 0.f;
#pragma unroll
            for (int k = 0; k < 4; k++)
                s = fmaf(src[j * H_DIM + lane + 32 * k], v4[k], s);
#pragma unroll
            for (int o = 16; o; o >>= 1) s += __shfl_xor_sync(0xffffffffu, s, o);
            if (lane == 0) sdot[half][w][j] = s;
        }
    }
    __syncthreads();

    if (tid < 8) {
        int hh = tid >> 2, h = tid & 3;
        float su = hsu[hh][h], sv = hsv[hh][h];
        float sc[GRP_N + 1];
        float s0 = su + sv;
        sc[0] = (s0 >= 0.f) ? s0 : 0.2f * s0;
        float mx = sc[0];
#pragma unroll
        for (int j = 0; j < GRP_N; j++) {
            float s = su + sdot[hh][h][j];
            s = (s >= 0.f) ? s : 0.2f * s;
            sc[j + 1] = s;
            mx = fmaxf(mx, s);
        }
        float sum = 0.f;
#pragma unroll
        for (int k = 0; k <= GRP_N; k++) { sc[k] = __expf(sc[k] - mx); sum += sc[k]; }
        float inv = __fdividef(1.f, sum);
#pragma unroll
        for (int k = 0; k <= GRP_N; k++) alpha[hh][h][k] = sc[k] * inv;
    }
    __syncthreads();

    {
        float macc[NH];
#pragma unroll
        for (int h = 0; h < NH; h++) macc[h] = alpha[half][h][0] * ahc;
        const float* src = gth + half * GRP_N * H_DIM;
#pragma unroll 4
        for (int j = 0; j < GRP_N; j++) {
            float gval = src[j * H_DIM + c];
#pragma unroll
            for (int h = 0; h < NH; h++)
                macc[h] = fmaf(alpha[half][h][j + 1], gval, macc[h]);
        }
#pragma unroll
        for (int h = 0; h < NH; h++)
            d_m[(size_t)p * G4H + h * H_DIM + c] = macc[h];
    }
}

// ---------------- g3: out = relu(0.25 * m_cat @ w_cat) + bias — split-K ----------------
__global__ __launch_bounds__(256) void g3_kernel(
    const float* __restrict__ gat_w, const float* __restrict__ gat_bias,
    float* __restrict__ out)
{
    __shared__ __align__(16) float m_sh[8][G4H];   // 16KB
    __shared__ __align__(16) ull red[3][8][64];    // 12KB
    int tid = threadIdx.x;
    int c2 = tid & 63;
    int kq = tid >> 6;
    int p0 = blockIdx.x * 8;

    {
        float4* dst = (float4*)&m_sh[0][0];
        const float4* src = (const float4*)&d_m[(size_t)p0 * G4H];
        for (int i = tid; i < 1024; i += 256) dst[i] = src[i];
    }
    __syncthreads();

    ull acc[8];
#pragma unroll
    for (int p = 0; p < 8; p++) acc[p] = 0ull;
    int k0 = kq * 128;
#pragma unroll 4
    for (int k = 0; k < 128; k++) {
        int kk = k0 + k;
        ull wv = *(const ull*)&gat_w[(size_t)kk * H_DIM + 2 * c2];
#pragma unroll
        for (int p = 0; p < 8; p++) {
            ull mp; PK2(mp, m_sh[p][kk]);
            FMA2(acc[p], mp, wv, acc[p]);
        }
    }
    if (kq) {
#pragma unroll
        for (int p = 0; p < 8; p++) red[kq - 1][p][c2] = acc[p];
    }
    __syncthreads();
    if (kq == 0) {
        float b0 = gat_bias[2 * c2], b1 = gat_bias[2 * c2 + 1];
#pragma unroll
        for (int p = 0; p < 8; p++) {
            ADD2(acc[p], acc[p], red[0][p][c2]);
            ADD2(acc[p], acc[p], red[1][p][c2]);
            ADD2(acc[p], acc[p], red[2][p][c2]);
            float lo, hi;
            UNPK2(lo, hi, acc[p]);
            float2 o2;
            o2.x = fmaxf(0.25f * lo, 0.f) + b0;
            o2.y = fmaxf(0.25f * hi, 0.f) + b1;
            *(float2*)&out[(size_t)(p0 + p) * H_DIM + 2 * c2] = o2;
        }
    }
}

// ---------------- host ----------------
extern "C" void kernel_launch(void* const* d_in, const int* in_sizes, int n_in,
                              void* d_out, int out_size)
{
    const float* obs         = (const float*)d_in[0];
    const float* goal_hidden = (const float*)d_in[1];
    const float* goal        = (const float*)d_in[2];
    const float* action      = (const float*)d_in[3];
    const float* h0          = (const float*)d_in[4];
    const float* c0          = (const float*)d_in[5];
    const float* W_emb       = (const float*)d_in[6];
    const float* b_emb       = (const float*)d_in[7];
    const float* W_ih        = (const float*)d_in[8];
    const float* W_hh        = (const float*)d_in[9];
    const float* b_ih        = (const float*)d_in[10];
    const float* b_hh        = (const float*)d_in[11];
    const float* W_dist      = (const float*)d_in[12];
    const float* b_dist      = (const float*)d_in[13];
    const float* W_gate      = (const float*)d_in[14];
    const float* b_gate      = (const float*)d_in[15];
    const float* gat_w       = (const float*)d_in[16];
    const float* gat_a       = (const float*)d_in[17];
    const float* gat_bias    = (const float*)d_in[18];
    float* out = (float*)d_out;

    const int LSTM_SMEM = 36864 + 32768;   // h_dup + red = 68 KB
    cudaFuncSetAttribute(lstm512x8, cudaFuncAttributeMaxDynamicSharedMemorySize, LSTM_SMEM);

    prep_kernel<<<PREP_BLKS + 128, 256>>>(W_hh, W_ih, b_ih, b_hh, gat_w, gat_a);
    xw_kernel<<<T_STEPS * N_PED / 32, 512>>>(obs, W_emb, b_emb);
    gateMLP<<<1024, 256>>>(goal, action, W_dist, b_dist, W_gate, b_gate);

    lstm512x8<<<N_PED / 16, 512, LSTM_SMEM>>>(h0, c0);

    gatB<<<1024, 256>>>(goal_hidden);
    g3_kernel<<<N_PED / 8, 256>>>(gat_w, gat_bias, out);
}

// round 15
// speedup vs baseline: 1.0674x; 1.0674x over previous
#include <cuda_runtime.h>
#include <math.h>

// Problem dims
#define T_STEPS 8
#define N_PED   2048
#define H_DIM   128
#define D_IN    64
#define G4H     512   // 4*H
#define N_GRP   64
#define GRP_N   32
#define DD_DIM  64
#define NH      4

typedef unsigned long long ull;

// packed f32x2 helpers (sm_100+)
#define FMA2(d, a, b, c) asm("fma.rn.f32x2 %0, %1, %2, %3;" : "=l"(d) : "l"(a), "l"(b), "l"(c))
#define ADD2(d, a, b) asm("add.rn.f32x2 %0, %1, %2;" : "=l"(d) : "l"(a), "l"(b))
#define PK2(dst, s) do { unsigned _u = __float_as_uint(s); \
    asm("mov.b64 %0, {%1, %1};" : "=l"(dst) : "r"(_u)); } while (0)
#define PKAB(dst, a, b) do { unsigned _ua = __float_as_uint(a), _ub = __float_as_uint(b); \
    asm("mov.b64 %0, {%1, %2};" : "=l"(dst) : "r"(_ua), "r"(_ub)); } while (0)
#define UNPK2(lo, hi, v) do { unsigned _a, _b; \
    asm("mov.b64 {%0, %1}, %2;" : "=r"(_a), "=r"(_b) : "l"(v)); \
    lo = __uint_as_float(_a); hi = __uint_as_float(_b); } while (0)

// ---------------- scratch (device globals; no allocation) ----------------
__device__ __align__(16) float d_wt2 [H_DIM * G4H];   // [k][ch][u]
__device__ __align__(16) float d_wit2[D_IN * G4H];
__device__ __align__(16) float d_bsum2[G4H];          // [ch][u]
__device__ __align__(16) float d_xw [T_STEPS * N_PED * G4H];  // bias + x@W_ih^T, permuted
__device__ __align__(16) float d_h [N_PED * H_DIM];
__device__ __align__(16) float d_th[N_PED * H_DIM];   // tanh(h)
__device__ __align__(16) float d_uv[2 * NH * H_DIM];  // u then v
__device__ __align__(16) float d_gate[N_PED * GRP_N * H_DIM];  // gate[p][j][c]
__device__ __align__(16) float d_m [N_PED * G4H];     // m_cat[p][h*128+f]

// ---------------- fast activations ----------------
__device__ __forceinline__ float sigf(float x) {
    return __fdividef(1.f, 1.f + __expf(-x));
}
__device__ __forceinline__ float tanh_f(float x) {
    return 1.f - __fdividef(2.f, __expf(2.f * x) + 1.f);
}

// ---------------- prep: weight permute (coalesced reads) + bias sum ----------------
#define PREP_BLKS 386
__global__ void prep_kernel(const float* __restrict__ W_hh, const float* __restrict__ W_ih,
                            const float* __restrict__ b_ih, const float* __restrict__ b_hh)
{
    int i = blockIdx.x * 256 + threadIdx.x;
    if (i < H_DIM * G4H) {
        int n = i >> 7, k = i & 127;          // coalesced read of W_hh[n][k]
        int ch = n & 127, u = n >> 7;
        d_wt2[k * G4H + ch * 4 + u] = W_hh[n * H_DIM + k];
        return;
    }
    int j = i - H_DIM * G4H;
    if (j < D_IN * G4H) {
        int n = j >> 6, k = j & 63;           // coalesced read of W_ih[n][k]
        int ch = n & 127, u = n >> 7;
        d_wit2[k * G4H + ch * 4 + u] = W_ih[n * D_IN + k];
        return;
    }
    int bb = j - D_IN * G4H;
    if (bb < G4H) {
        int ch = bb >> 2, u = bb & 3;
        int n = u * 128 + ch;
        d_bsum2[bb] = b_ih[n] + b_hh[n];
    }
}

// ================= MID fat kernel: gateMLP | xw | uv (all throughput-bound) =================
#define MID_GATE 1024
#define MID_XW   1024
#define MID_UV   128
#define MID_GRID (MID_GATE + MID_XW + MID_UV)

__global__ __launch_bounds__(256) void mid_kernel(
    const float* __restrict__ obs,
    const float* __restrict__ W_emb, const float* __restrict__ b_emb,
    const float* __restrict__ goal, const float* __restrict__ action,
    const float* __restrict__ W_dist, const float* __restrict__ b_dist,
    const float* __restrict__ W_gate, const float* __restrict__ b_gate,
    const float* __restrict__ gat_w, const float* __restrict__ gat_a)
{
    __shared__ __align__(16) char sraw[25600];
    int tid = threadIdx.x;
    int b = blockIdx.x;

    if (b < MID_GATE) {
        // ---------------- gate MLP branch ----------------
        float* t_sh = (float*)sraw;                 // 8KB
        float* s_sh = (float*)(sraw + 8192);        // 512B
        float* r_sh = (float*)(sraw + 8704);        // 16KB
        float* pax  = (float*)(sraw + 25088);       // 4*32*4 = 512B
        float* pay  = pax + 32;
        float* pgx  = pax + 64;
        float* pgy  = pax + 96;

        int g  = b >> 4;
        int ip = b & 15;
        int half = tid >> 7;
        int c    = tid & 127;
        int i_loc = 2 * ip + half;
        int p = g * GRP_N + i_loc;

        if (tid < GRP_N) {
            int q = g * GRP_N + tid;
            pax[tid] = action[q * 2 + 0]; pay[tid] = action[q * 2 + 1];
            pgx[tid] = goal[q * 2 + 0];   pgy[tid] = goal[q * 2 + 1];
        }
        __syncthreads();
        for (int idx = tid; idx < GRP_N * DD_DIM; idx += 256) {
            int j = idx >> 6, d = idx & 63;
            float t = fmaf(pax[j], W_dist[4 * 64 + d],
                      fmaf(pay[j], W_dist[5 * 64 + d],
                      fmaf(pgx[j], W_dist[6 * 64 + d],
                           pgy[j] * W_dist[7 * 64 + d])));
            t_sh[idx] = t;
        }
        if (tid < 2 * DD_DIM) {
            int hh = tid >> 6, d = tid & 63;
            int il = 2 * ip + hh;
            float s = b_dist[d];
            s = fmaf(pax[il], W_dist[0 * 64 + d], s);
            s = fmaf(pay[il], W_dist[1 * 64 + d], s);
            s = fmaf(pgx[il], W_dist[2 * 64 + d], s);
            s = fmaf(pgy[il], W_dist[3 * 64 + d], s);
            s_sh[tid] = s;
        }
        __syncthreads();
        for (int idx = tid; idx < 2 * GRP_N * DD_DIM; idx += 256) {
            int hh = idx >> 11, jd = idx & 2047;
            r_sh[idx] = fmaxf(s_sh[hh * 64 + (jd & 63)] + t_sh[jd], 0.f);
        }
        __syncthreads();

        float bg = b_gate[c];
        const float* rbase = r_sh + half * GRP_N * DD_DIM;
        float* gout = d_gate + (size_t)p * GRP_N * H_DIM;
#pragma unroll
        for (int jt = 0; jt < 4; jt++) {
            int j0 = jt * 8;
            ull acc2[8];
#pragma unroll
            for (int jj = 0; jj < 8; jj++) acc2[jj] = 0ull;
            for (int d0 = 0; d0 < DD_DIM; d0 += 4) {
                float w0 = W_gate[(d0 + 0) * H_DIM + c];
                float w1 = W_gate[(d0 + 1) * H_DIM + c];
                float w2 = W_gate[(d0 + 2) * H_DIM + c];
                float w3 = W_gate[(d0 + 3) * H_DIM + c];
                ull ww0, ww1;
                PKAB(ww0, w0, w1);
                PKAB(ww1, w2, w3);
#pragma unroll
                for (int jj = 0; jj < 8; jj++) {
                    ulonglong2 rv = *(const ulonglong2*)&rbase[(j0 + jj) * DD_DIM + d0];
                    FMA2(acc2[jj], rv.x, ww0, acc2[jj]);
                    FMA2(acc2[jj], rv.y, ww1, acc2[jj]);
                }
            }
#pragma unroll
            for (int jj = 0; jj < 8; jj++) {
                float lo, hi;
                UNPK2(lo, hi, acc2[jj]);
                gout[(j0 + jj) * H_DIM + c] = sigf(lo + hi + bg);
            }
        }
    } else if (b < MID_GATE + MID_XW) {
        // ---------------- xw branch: d_xw = bias + embed(obs) @ W_ih^T ----------------
        // 16 peds per block: t = b2>>7, p0 = (b2&127)*16. ch = tid&127, ty = tid>>7.
        ull (*x_dup)[16] = (ull (*)[16])sraw;   // [64][16] = 8 KB
        int b2 = b - MID_GATE;
        int t  = b2 >> 7;
        int p0 = (b2 & 127) * 16;
        int ch = tid & 127, ty = tid >> 7;

        for (int i = tid; i < 16 * D_IN; i += 256) {
            int r = i & 15, c = i >> 4;
            const float* op = obs + ((size_t)t * N_PED + p0 + r) * 2;
            float v = fmaxf(fmaf(op[0], W_emb[c], fmaf(op[1], W_emb[64 + c], b_emb[c])), 0.f);
            ull dv; PKAB(dv, v, v);
            x_dup[c][r] = dv;
        }
        ulonglong2 bi = *(const ulonglong2*)&d_bsum2[ch * 4];
        __syncthreads();

        const ulonglong2* wi2 = (const ulonglong2*)d_wit2;
        ull acc[8][2];
#pragma unroll
        for (int p = 0; p < 8; p++) { acc[p][0] = bi.x; acc[p][1] = bi.y; }
#pragma unroll 8
        for (int k = 0; k < D_IN; k++) {
            ulonglong2 wv = wi2[k * 128 + ch];
            const ull* xrow = &x_dup[k][8 * ty];
            ulonglong2 xA = *(const ulonglong2*)&xrow[0];
            ulonglong2 xB = *(const ulonglong2*)&xrow[2];
            ulonglong2 xC = *(const ulonglong2*)&xrow[4];
            ulonglong2 xD = *(const ulonglong2*)&xrow[6];
            FMA2(acc[0][0], xA.x, wv.x, acc[0][0]); FMA2(acc[0][1], xA.x, wv.y, acc[0][1]);
            FMA2(acc[1][0], xA.y, wv.x, acc[1][0]); FMA2(acc[1][1], xA.y, wv.y, acc[1][1]);
            FMA2(acc[2][0], xB.x, wv.x, acc[2][0]); FMA2(acc[2][1], xB.x, wv.y, acc[2][1]);
            FMA2(acc[3][0], xB.y, wv.x, acc[3][0]); FMA2(acc[3][1], xB.y, wv.y, acc[3][1]);
            FMA2(acc[4][0], xC.x, wv.x, acc[4][0]); FMA2(acc[4][1], xC.x, wv.y, acc[4][1]);
            FMA2(acc[5][0], xC.y, wv.x, acc[5][0]); FMA2(acc[5][1], xC.y, wv.y, acc[5][1]);
            FMA2(acc[6][0], xD.x, wv.x, acc[6][0]); FMA2(acc[6][1], xD.x, wv.y, acc[6][1]);
            FMA2(acc[7][0], xD.y, wv.x, acc[7][0]); FMA2(acc[7][1], xD.y, wv.y, acc[7][1]);
        }
#pragma unroll
        for (int p = 0; p < 8; p++) {
            ulonglong2 o2; o2.x = acc[p][0]; o2.y = acc[p][1];
            *(ulonglong2*)&d_xw[((size_t)t * N_PED + p0 + 8 * ty + p) * G4H + ch * 4] = o2;
        }
    } else {
        // ---------------- uv branch: u_h = w_h@a1, v_h = w_h@a2 ----------------
        int w = (b - MID_GATE - MID_XW) * 8 + (tid >> 5);   // 0..1023
        int lane = tid & 31;
        int sel = w >> 9;
        int h   = (w >> 7) & 3;
        int c   = w & 127;
        const float* a  = gat_a + sel * H_DIM;
        const float* wp = gat_w + ((size_t)h * H_DIM + c) * H_DIM;
        float s = 0.f;
#pragma unroll
        for (int o = lane; o < H_DIM; o += 32) s = fmaf(wp[o], a[o], s);
#pragma unroll
        for (int o = 16; o; o >>= 1) s += __shfl_xor_sync(0xffffffffu, s, o);
        if (lane == 0) d_uv[sel * (NH * H_DIM) + h * H_DIM + c] = s;
    }
}

// ---------------- 8-step LSTM, recurrent-only: 512 threads, 8 peds/thread, split-K ----------------
#define HP 18   // h row pitch in ull
__global__ __launch_bounds__(512) void lstm512x8(
    const float* __restrict__ h0, const float* __restrict__ c0)
{
    extern __shared__ __align__(16) char sraw[];
    ull (*h_dup)[H_DIM][HP] = (ull (*)[H_DIM][HP])sraw;                // 36 KB
    ull (*red)[8][256]      = (ull (*)[8][256])(sraw + 36864);         // 32 KB

    int tid = threadIdx.x;
    int ch = tid & 127;
    int ty = (tid >> 7) & 1;
    int kh = tid >> 8;
    int p0 = blockIdx.x * 16;

    // stage h0 (duplicated)
    for (int i = tid; i < 16 * H_DIM; i += 512) {
        int r = i & 15;
        int k = i >> 4;
        float v = h0[(size_t)(p0 + r) * H_DIM + k];
        ull dv; PKAB(dv, v, v);
        h_dup[0][k][r] = dv;
    }
    float c_reg[4];
#pragma unroll
    for (int q = 0; q < 4; q++)
        c_reg[q] = c0[(size_t)(p0 + 8 * ty + kh * 4 + q) * H_DIM + ch];
    __syncthreads();

    const ulonglong2* wt2 = (const ulonglong2*)d_wt2;   // idx k*128 + ch
    int idx = ty * 128 + ch;
    int kbR = kh * 64;

    for (int t = 0; t < T_STEPS; t++) {
        int cur = t & 1, nxt = cur ^ 1;
        ulonglong2 xwv[4];
#pragma unroll
        for (int q = 0; q < 4; q++) {
            int pq = kh * 4 + q;
            xwv[q] = *(const ulonglong2*)&d_xw[((size_t)t * N_PED + p0 + 8 * ty + pq) * G4H + ch * 4];
        }
        ull acc[8][2];
#pragma unroll
        for (int p = 0; p < 8; p++) { acc[p][0] = 0ull; acc[p][1] = 0ull; }
#pragma unroll 8
        for (int k = 0; k < 64; k++) {
            int kk = kbR + k;
            ulonglong2 wv = wt2[kk * 128 + ch];
            const ull* hrow = &h_dup[cur][kk][8 * ty];
            ulonglong2 hA = *(const ulonglong2*)&hrow[0];
            ulonglong2 hB = *(const ulonglong2*)&hrow[2];
            ulonglong2 hC = *(const ulonglong2*)&hrow[4];
            ulonglong2 hD = *(const ulonglong2*)&hrow[6];
            FMA2(acc[0][0], hA.x, wv.x, acc[0][0]); FMA2(acc[0][1], hA.x, wv.y, acc[0][1]);
            FMA2(acc[1][0], hA.y, wv.x, acc[1][0]); FMA2(acc[1][1], hA.y, wv.y, acc[1][1]);
            FMA2(acc[2][0], hB.x, wv.x, acc[2][0]); FMA2(acc[2][1], hB.x, wv.y, acc[2][1]);
            FMA2(acc[3][0], hB.y, wv.x, acc[3][0]); FMA2(acc[3][1], hB.y, wv.y, acc[3][1]);
            FMA2(acc[4][0], hC.x, wv.x, acc[4][0]); FMA2(acc[4][1], hC.x, wv.y, acc[4][1]);
            FMA2(acc[5][0], hC.y, wv.x, acc[5][0]); FMA2(acc[5][1], hC.y, wv.y, acc[5][1]);
            FMA2(acc[6][0], hD.x, wv.x, acc[6][0]); FMA2(acc[6][1], hD.x, wv.y, acc[6][1]);
            FMA2(acc[7][0], hD.y, wv.x, acc[7][0]); FMA2(acc[7][1], hD.y, wv.y, acc[7][1]);
        }
        if (kh == 0) {
#pragma unroll
            for (int q = 0; q < 4; q++) {
                red[0][q * 2 + 0][idx] = acc[4 + q][0];
                red[0][q * 2 + 1][idx] = acc[4 + q][1];
            }
        } else {
#pragma unroll
            for (int q = 0; q < 4; q++) {
                red[1][q * 2 + 0][idx] = acc[q][0];
                red[1][q * 2 + 1][idx] = acc[q][1];
            }
        }
        __syncthreads();
#pragma unroll
        for (int q = 0; q < 4; q++) {
            int pq = kh * 4 + q;
            ull a0 = acc[pq][0], a1 = acc[pq][1];
            ADD2(a0, a0, red[1 - kh][q * 2 + 0][idx]);
            ADD2(a1, a1, red[1 - kh][q * 2 + 1][idx]);
            ADD2(a0, a0, xwv[q].x);
            ADD2(a1, a1, xwv[q].y);
            float iv, fv, gv, ov;
            UNPK2(iv, fv, a0);
            UNPK2(gv, ov, a1);
            float cn = sigf(fv) * c_reg[q] + sigf(iv) * tanh_f(gv);
            c_reg[q] = cn;
            float hv = sigf(ov) * tanh_f(cn);
            ull dv; PKAB(dv, hv, hv);
            h_dup[nxt][ch][8 * ty + pq] = dv;
        }
        __syncthreads();
    }
    for (int i = tid; i < 16 * H_DIM; i += 512) {
        int k = i & 127;
        int r = i >> 7;
        float v = __uint_as_float((unsigned)(h_dup[0][k][r] & 0xffffffffull));
        d_h [(size_t)(p0 + r) * H_DIM + k] = v;
        d_th[(size_t)(p0 + r) * H_DIM + k] = tanh_f(v);
    }
}

// ---------------- KERNEL B: h-dependent GAT ----------------
__global__ __launch_bounds__(256) void gatB(const float* __restrict__ goal_hidden)
{
    __shared__ __align__(16) float gth[2 * GRP_N * H_DIM];  // 32KB
    __shared__ float ah_sh[2][H_DIM];
    __shared__ float sdot[2][NH][GRP_N];
    __shared__ float alpha[2][NH][GRP_N + 1];
    __shared__ float hsu[2][NH], hsv[2][NH];

    int tid = threadIdx.x;
    int b = blockIdx.x;
    int g  = b >> 4;
    int ip = b & 15;
    int half = tid >> 7;
    int c    = tid & 127;
    int i_loc = 2 * ip + half;
    int p = g * GRP_N + i_loc;

    float ahc = d_h[(size_t)p * H_DIM + c];
    float ghc = goal_hidden[(size_t)p * H_DIM + c];
    ah_sh[half][c] = ahc;

    {
        const float* gp = d_gate + (size_t)p * GRP_N * H_DIM;
        float* dst = gth + half * GRP_N * H_DIM;
#pragma unroll 4
        for (int j = 0; j < GRP_N; j++) {
            float v = gp[j * H_DIM + c] * d_th[(size_t)(g * GRP_N + j) * H_DIM + c];
            dst[j * H_DIM + c] = (j == i_loc) ? ghc : v;
        }
    }
    __syncthreads();

    {
        int t128 = tid & 127, w = t128 >> 5, lane = t128 & 31;
        const float* uh = d_uv + w * H_DIM;
        const float* vh = d_uv + NH * H_DIM + w * H_DIM;
        float u4[4], v4[4], a4[4];
#pragma unroll
        for (int k = 0; k < 4; k++) {
            int cc = lane + 32 * k;
            u4[k] = uh[cc]; v4[k] = vh[cc];
            a4[k] = ah_sh[half][cc];
        }
        float su = 0.f, sv = 0.f;
#pragma unroll
        for (int k = 0; k < 4; k++) { su = fmaf(a4[k], u4[k], su); sv = fmaf(a4[k], v4[k], sv); }
#pragma unroll
        for (int o = 16; o; o >>= 1) {
            su += __shfl_xor_sync(0xffffffffu, su, o);
            sv += __shfl_xor_sync(0xffffffffu, sv, o);
        }
        if (lane == 0) { hsu[half][w] = su; hsv[half][w] = sv; }
        const float* src = gth + half * GRP_N * H_DIM;
        for (int j = 0; j < GRP_N; j++) {
            float s = 0.f;
#pragma unroll
            for (int k = 0; k < 4; k++)
                s = fmaf(src[j * H_DIM + lane + 32 * k], v4[k], s);
#pragma unroll
            for (int o = 16; o; o >>= 1) s += __shfl_xor_sync(0xffffffffu, s, o);
            if (lane == 0) sdot[half][w][j] = s;
        }
    }
    __syncthreads();

    if (tid < 8) {
        int hh = tid >> 2, h = tid & 3;
        float su = hsu[hh][h], sv = hsv[hh][h];
        float sc[GRP_N + 1];
        float s0 = su + sv;
        sc[0] = (s0 >= 0.f) ? s0 : 0.2f * s0;
        float mx = sc[0];
#pragma unroll
        for (int j = 0; j < GRP_N; j++) {
            float s = su + sdot[hh][h][j];
            s = (s >= 0.f) ? s : 0.2f * s;
            sc[j + 1] = s;
            mx = fmaxf(mx, s);
        }
        float sum = 0.f;
#pragma unroll
        for (int k = 0; k <= GRP_N; k++) { sc[k] = __expf(sc[k] - mx); sum += sc[k]; }
        float inv = __fdividef(1.f, sum);
#pragma unroll
        for (int k = 0; k <= GRP_N; k++) alpha[hh][h][k] = sc[k] * inv;
    }
    __syncthreads();

    {
        float macc[NH];
#pragma unroll
        for (int h = 0; h < NH; h++) macc[h] = alpha[half][h][0] * ahc;
        const float* src = gth + half * GRP_N * H_DIM;
#pragma unroll 4
        for (int j = 0; j < GRP_N; j++) {
            float gval = src[j * H_DIM + c];
#pragma unroll
            for (int h = 0; h < NH; h++)
                macc[h] = fmaf(alpha[half][h][j + 1], gval, macc[h]);
        }
#pragma unroll
        for (int h = 0; h < NH; h++)
            d_m[(size_t)p * G4H + h * H_DIM + c] = macc[h];
    }
}

// ---------------- g3: out = relu(0.25 * m_cat @ w_cat) + bias — split-K ----------------
__global__ __launch_bounds__(256) void g3_kernel(
    const float* __restrict__ gat_w, const float* __restrict__ gat_bias,
    float* __restrict__ out)
{
    __shared__ __align__(16) float m_sh[8][G4H];   // 16KB
    __shared__ __align__(16) ull red[3][8][64];    // 12KB
    int tid = threadIdx.x;
    int c2 = tid & 63;
    int kq = tid >> 6;
    int p0 = blockIdx.x * 8;

    {
        float4* dst = (float4*)&m_sh[0][0];
        const float4* src = (const float4*)&d_m[(size_t)p0 * G4H];
        for (int i = tid; i < 1024; i += 256) dst[i] = src[i];
    }
    __syncthreads();

    ull acc[8];
#pragma unroll
    for (int p = 0; p < 8; p++) acc[p] = 0ull;
    int k0 = kq * 128;
#pragma unroll 4
    for (int k = 0; k < 128; k++) {
        int kk = k0 + k;
        ull wv = *(const ull*)&gat_w[(size_t)kk * H_DIM + 2 * c2];
#pragma unroll
        for (int p = 0; p < 8; p++) {
            ull mp; PK2(mp, m_sh[p][kk]);
            FMA2(acc[p], mp, wv, acc[p]);
        }
    }
    if (kq) {
#pragma unroll
        for (int p = 0; p < 8; p++) red[kq - 1][p][c2] = acc[p];
    }
    __syncthreads();
    if (kq == 0) {
        float b0 = gat_bias[2 * c2], b1 = gat_bias[2 * c2 + 1];
#pragma unroll
        for (int p = 0; p < 8; p++) {
            ADD2(acc[p], acc[p], red[0][p][c2]);
            ADD2(acc[p], acc[p], red[1][p][c2]);
            ADD2(acc[p], acc[p], red[2][p][c2]);
            float lo, hi;
            UNPK2(lo, hi, acc[p]);
            float2 o2;
            o2.x = fmaxf(0.25f * lo, 0.f) + b0;
            o2.y = fmaxf(0.25f * hi, 0.f) + b1;
            *(float2*)&out[(size_t)(p0 + p) * H_DIM + 2 * c2] = o2;
        }
    }
}

// ---------------- host ----------------
extern "C" void kernel_launch(void* const* d_in, const int* in_sizes, int n_in,
                              void* d_out, int out_size)
{
    const float* obs         = (const float*)d_in[0];
    const float* goal_hidden = (const float*)d_in[1];
    const float* goal        = (const float*)d_in[2];
    const float* action      = (const float*)d_in[3];
    const float* h0          = (const float*)d_in[4];
    const float* c0          = (const float*)d_in[5];
    const float* W_emb       = (const float*)d_in[6];
    const float* b_emb       = (const float*)d_in[7];
    const float* W_ih        = (const float*)d_in[8];
    const float* W_hh        = (const float*)d_in[9];
    const float* b_ih        = (const float*)d_in[10];
    const float* b_hh        = (const float*)d_in[11];
    const float* W_dist      = (const float*)d_in[12];
    const float* b_dist      = (const float*)d_in[13];
    const float* W_gate      = (const float*)d_in[14];
    const float* b_gate      = (const float*)d_in[15];
    const float* gat_w       = (const float*)d_in[16];
    const float* gat_a       = (const float*)d_in[17];
    const float* gat_bias    = (const float*)d_in[18];
    float* out = (float*)d_out;

    const int LSTM_SMEM = 36864 + 32768;   // h_dup + red = 68 KB
    cudaFuncSetAttribute(lstm512x8, cudaFuncAttributeMaxDynamicSharedMemorySize, LSTM_SMEM);

    // serial predecessor: weight permute + bias (small)
    prep_kernel<<<PREP_BLKS, 256>>>(W_hh, W_ih, b_ih, b_hh);

    // co-scheduled throughput work: gateMLP | xw | uv
    mid_kernel<<<MID_GRID, 256>>>(obs, W_emb, b_emb, goal, action,
                                  W_dist, b_dist, W_gate, b_gate, gat_w, gat_a);

    // sequential LSTM (recurrent-only)
    lstm512x8<<<N_PED / 16, 512, LSTM_SMEM>>>(h0, c0);

    gatB<<<1024, 256>>>(goal_hidden);
    g3_kernel<<<N_PED / 8, 256>>>(gat_w, gat_bias, out);
}